// round 17
// baseline (speedup 1.0000x reference)
#include <cuda_runtime.h>
#include <cuda_fp16.h>
#include <cstdint>

#define NN 100000
#define EE 3200000
#define IN_CH 256
#define HID 64
#define OUTC 32

#define SCAN_B 1024
#define NBLK ((NN + SCAN_B - 1) / SCAN_B)   // 98

// ---------------- scratch (no allocations allowed) ----------------
__device__ int      d_is64;                   // 1 if edge_index is int64, else 0
__device__ unsigned d_done;                   // bsum completion counter
__device__ __align__(16) int   d_cnt[NN];     // in-degree (edges only)
__device__ __align__(16) int   d_off[NN];     // CSR start offsets
__device__ __align__(16) int   d_cur[NN];     // fill cursors
__device__ __align__(16) int   d_erow[EE];    // CSR payload: source node per edge
__device__ __align__(16) int   d_bsum[NBLK];  // per-block count sums
__device__ __align__(16) int   d_boff[NBLK];  // scanned block offsets
__device__ __align__(16) float d_dis[NN];
__device__ __align__(16) unsigned d_g1h[(size_t)NN * 32];   // half2-packed dis*(x@W1)
__device__ __align__(16) unsigned d_g2h[(size_t)NN * 16];   // half2-packed dis*(h1@W2)

// ---------------- tf32 convert (round-to-nearest) ----------------
__device__ __forceinline__ float to_tf32(float f) {
    unsigned u;
    asm("cvt.rna.tf32.f32 %0, %1;" : "=r"(u) : "f"(f));
    return __uint_as_float(u);
}

// m16n8k8 tf32 MMA, explicit fragments (PTX ISA layout)
__device__ __forceinline__ void mma_tf32(float c[4], unsigned a0, unsigned a1,
                                         unsigned a2, unsigned a3,
                                         unsigned b0, unsigned b1) {
    asm volatile(
        "mma.sync.aligned.m16n8k8.row.col.f32.tf32.tf32.f32 "
        "{%0,%1,%2,%3}, {%4,%5,%6,%7}, {%8,%9}, {%0,%1,%2,%3};"
        : "+f"(c[0]), "+f"(c[1]), "+f"(c[2]), "+f"(c[3])
        : "r"(a0), "r"(a1), "r"(a2), "r"(a3), "r"(b0), "r"(b1));
}

// ---------------- zero histogram + reset counter + dtype detect ----------------
__global__ void k_zero(const int* __restrict__ ei_w) {
    unsigned i = blockIdx.x * blockDim.x + threadIdx.x;
    if (i < (unsigned)NN) d_cnt[i] = 0;
    if (blockIdx.x == 0 && threadIdx.x < 32) {
        int lane = threadIdx.x;
        if (lane == 0) d_done = 0;
        int nz = 0;
#pragma unroll
        for (int j = 0; j < 8; j++) {
            long long k = (long long)(lane * 8 + j) * (EE / 512);  // < EE/2
            nz |= ei_w[2 * k + 1];
        }
        unsigned any = __ballot_sync(0xffffffffu, nz != 0);
        if (lane == 0) d_is64 = (any == 0u) ? 1 : 0;
    }
}

// ---------------- histogram by target (col), 4 edges/thread ----------------
__global__ void k_hist(const void* __restrict__ ei) {
    unsigned e0 = (blockIdx.x * blockDim.x + threadIdx.x) * 4u;
    if (e0 >= (unsigned)EE) return;  // EE % 4 == 0
    int c[4];
    if (d_is64) {
        const long long* p = (const long long*)ei + EE;
#pragma unroll
        for (int u = 0; u < 4; u++) c[u] = (int)p[e0 + u];
    } else {
        const int* p = (const int*)ei + EE;
#pragma unroll
        for (int u = 0; u < 4; u++) c[u] = p[e0 + u];
    }
#pragma unroll
    for (int u = 0; u < 4; u++) atomicAdd(&d_cnt[c[u]], 1);
}

// ---------------- scan phase 1+2: per-block sums, last block scans ----------------
__global__ __launch_bounds__(SCAN_B) void k_bsum() {
    __shared__ int sred[SCAN_B / 32];
    __shared__ int sscan[128];
    __shared__ int slast;
    int t = threadIdx.x;
    unsigned i = blockIdx.x * SCAN_B + t;
    int c = (i < (unsigned)NN) ? d_cnt[i] : 0;
    int w = c;
#pragma unroll
    for (int off = 16; off; off >>= 1) w += __shfl_xor_sync(0xffffffffu, w, off);
    if ((t & 31) == 0) sred[t >> 5] = w;
    __syncthreads();
    if (t < 32) {
        int s = (t < SCAN_B / 32) ? sred[t] : 0;
#pragma unroll
        for (int off = 16; off; off >>= 1) s += __shfl_xor_sync(0xffffffffu, s, off);
        if (t == 0) {
            d_bsum[blockIdx.x] = s;
            __threadfence();
            slast = (atomicAdd(&d_done, 1u) == (unsigned)(NBLK - 1));
        }
    }
    __syncthreads();
    if (!slast) return;
    // last block: exclusive-scan the 98 block sums
    if (t < 128) sscan[t] = (t < NBLK) ? d_bsum[t] : 0;
    __syncthreads();
#pragma unroll
    for (int off = 1; off < 128; off <<= 1) {
        int v = 0;
        if (t < 128 && t >= off) v = sscan[t - off];
        __syncthreads();
        if (t < 128) sscan[t] += v;
        __syncthreads();
    }
    if (t < NBLK) d_boff[t] = (t == 0) ? 0 : sscan[t - 1];
}

// ---------------- scan phase 3: intra-block exclusive scan + finalize ----------------
__global__ __launch_bounds__(SCAN_B) void k_off() {
    __shared__ int swsum[SCAN_B / 32];
    int t = threadIdx.x;
    int lane = t & 31;
    int wp = t >> 5;
    unsigned i = blockIdx.x * SCAN_B + t;
    int c = (i < (unsigned)NN) ? d_cnt[i] : 0;
    int s = c;
#pragma unroll
    for (int off = 1; off < 32; off <<= 1) {
        int v = __shfl_up_sync(0xffffffffu, s, off);
        if (lane >= off) s += v;
    }
    if (lane == 31) swsum[wp] = s;
    __syncthreads();
    if (t < 32) {
        int ws = (t < SCAN_B / 32) ? swsum[t] : 0;
#pragma unroll
        for (int off = 1; off < 32; off <<= 1) {
            int v = __shfl_up_sync(0xffffffffu, ws, off);
            if ((t & 31) >= off) ws += v;
        }
        if (t < SCAN_B / 32) swsum[t] = ws;
    }
    __syncthreads();
    int excl = s - c + (wp ? swsum[wp - 1] : 0) + d_boff[blockIdx.x];
    if (i < (unsigned)NN) {
        d_off[i] = excl;
        d_cur[i] = excl;
        d_dis[i] = rsqrtf((float)(c + 1));  // +1 self loop
    }
}

// ---------------- fill CSR, 4 edges per thread (MLP) ----------------
__global__ void k_fill(const void* __restrict__ ei) {
    unsigned e0 = (blockIdx.x * blockDim.x + threadIdx.x) * 4u;
    if (e0 >= (unsigned)EE) return;
    int r[4], c[4];
    if (d_is64) {
        const long long* p = (const long long*)ei;
#pragma unroll
        for (int u = 0; u < 4; u++) {
            r[u] = (int)p[e0 + u];
            c[u] = (int)p[(size_t)EE + e0 + u];
        }
    } else {
        const int* p = (const int*)ei;
#pragma unroll
        for (int u = 0; u < 4; u++) {
            r[u] = p[e0 + u];
            c[u] = p[EE + e0 + u];
        }
    }
#pragma unroll
    for (int u = 0; u < 4; u++) {
        int pos = atomicAdd(&d_cur[c[u]], 1);
        d_erow[pos] = r[u];
    }
}

// ---------------- GEMM1 (manual tf32 mma.m16n8k8): g1h = fp16(dis * (x @ W1)) ----------------
#define A_LD 36   // 36 % 32 == 4 -> a-frag banks 4g+t, all distinct
#define B_LD 72   // 72 % 32 == 8 -> b-frag banks 8t+g, all distinct
__global__ __launch_bounds__(128) void k_gemm1(const float* __restrict__ x,
                                               const float* __restrict__ W1) {
    __shared__ __align__(16) float sA[64 * A_LD];
    __shared__ __align__(16) float sB[32 * B_LD];
    int tid = threadIdx.x;
    int warp = tid >> 5;
    int lane = tid & 31;
    int g = lane >> 2;
    int t = lane & 3;
    int m0 = blockIdx.x * 64;

    float c[8][4];
#pragma unroll
    for (int j = 0; j < 8; j++)
#pragma unroll
        for (int q = 0; q < 4; q++) c[j][q] = 0.f;

    for (int k0 = 0; k0 < IN_CH; k0 += 32) {
#pragma unroll
        for (int i = 0; i < 4; i++) {
            int idx = tid + i * 128;
            int r = idx >> 3;
            int cq = (idx & 7) * 4;
            int gm = m0 + r;
            float4 v = make_float4(0.f, 0.f, 0.f, 0.f);
            if (gm < NN) v = *(const float4*)(x + (size_t)gm * IN_CH + k0 + cq);
            float* dst = sA + r * A_LD + cq;
            dst[0] = to_tf32(v.x); dst[1] = to_tf32(v.y);
            dst[2] = to_tf32(v.z); dst[3] = to_tf32(v.w);
        }
#pragma unroll
        for (int i = 0; i < 4; i++) {
            int idx = tid + i * 128;
            int r = idx >> 4;
            int cq = (idx & 15) * 4;
            float4 w = *(const float4*)(W1 + (size_t)(k0 + r) * HID + cq);
            float* dst = sB + r * B_LD + cq;
            dst[0] = to_tf32(w.x); dst[1] = to_tf32(w.y);
            dst[2] = to_tf32(w.z); dst[3] = to_tf32(w.w);
        }
        __syncthreads();
#pragma unroll
        for (int kk = 0; kk < 32; kk += 8) {
            int abase = (warp * 16 + g) * A_LD + kk + t;
            unsigned a0 = __float_as_uint(sA[abase]);
            unsigned a1 = __float_as_uint(sA[abase + 8 * A_LD]);
            unsigned a2 = __float_as_uint(sA[abase + 4]);
            unsigned a3 = __float_as_uint(sA[abase + 8 * A_LD + 4]);
#pragma unroll
            for (int j = 0; j < 8; j++) {
                unsigned b0 = __float_as_uint(sB[(kk + t) * B_LD + j * 8 + g]);
                unsigned b1 = __float_as_uint(sB[(kk + t + 4) * B_LD + j * 8 + g]);
                mma_tf32(c[j], a0, a1, a2, a3, b0, b1);
            }
        }
        __syncthreads();
    }

    int row0 = m0 + warp * 16 + g;
    int row1 = row0 + 8;
    bool p0 = row0 < NN, p1 = row1 < NN;
    float s0 = p0 ? d_dis[row0] : 0.f;
    float s1 = p1 ? d_dis[row1] : 0.f;
#pragma unroll
    for (int j = 0; j < 8; j++) {
        int col = j * 8 + 2 * t;
        if (p0) {
            __half2 h = __floats2half2_rn(s0 * c[j][0], s0 * c[j][1]);
            d_g1h[(size_t)row0 * 32 + (col >> 1)] = *(unsigned*)&h;
        }
        if (p1) {
            __half2 h = __floats2half2_rn(s1 * c[j][2], s1 * c[j][3]);
            d_g1h[(size_t)row1 * 32 + (col >> 1)] = *(unsigned*)&h;
        }
    }
}

// ---------------- agg1: 4 edges/warp via quarter-warps, uint4/lane + ELU + GEMM2 ----------------
// Quarter q = lane>>3 handles edges jj = 4u+q; lane ql=lane&7 owns features [ql*8, ql*8+8).
__global__ __launch_bounds__(256) void k_agg1(const float* __restrict__ b1,
                                              const float* __restrict__ W2) {
    __shared__ float sW[64][32];   // W2
    __shared__ float sh[8][64];    // h per warp
    int t = threadIdx.x;
    int warp = t >> 5;
    int lane = t & 31;
    ((float4*)sW)[t] = ((const float4*)W2)[t];
    ((float4*)sW)[t + 256] = ((const float4*)W2)[t + 256];
    __syncthreads();

    int v = blockIdx.x * 8 + warp;
    if (v >= NN) return;

    int start = d_off[v];
    int cnt = d_cnt[v];
    int q = lane >> 3;      // quarter id 0..3
    int ql = lane & 7;      // lane within quarter

    float acc[8];
#pragma unroll
    for (int i = 0; i < 8; i++) acc[i] = 0.f;
    if (q == 0) {  // self term (fp16 shadow)
        uint4 sv = *(const uint4*)&d_g1h[(size_t)v * 32 + ql * 4];
        float2 f0 = __half22float2(*(__half2*)&sv.x);
        float2 f1 = __half22float2(*(__half2*)&sv.y);
        float2 f2 = __half22float2(*(__half2*)&sv.z);
        float2 f3 = __half22float2(*(__half2*)&sv.w);
        acc[0] = f0.x; acc[1] = f0.y; acc[2] = f1.x; acc[3] = f1.y;
        acc[4] = f2.x; acc[5] = f2.y; acc[6] = f3.x; acc[7] = f3.y;
    }

    for (int base = 0; base < cnt; base += 32) {
        int nb = cnt - base; if (nb > 32) nb = 32;
        int er = (lane < nb) ? d_erow[start + base + lane] : 0;
        uint4 g[8];
        bool pv[8];
#pragma unroll
        for (int u = 0; u < 8; u++) {
            int jj = 4 * u + q;
            int r = __shfl_sync(0xffffffffu, er, jj);
            pv[u] = jj < nb;
            r = pv[u] ? r : v;  // in-range dummy
            g[u] = *(const uint4*)&d_g1h[(size_t)r * 32 + ql * 4];
        }
#pragma unroll
        for (int u = 0; u < 8; u++) {
            if (pv[u]) {
                float2 f0 = __half22float2(*(__half2*)&g[u].x);
                float2 f1 = __half22float2(*(__half2*)&g[u].y);
                float2 f2 = __half22float2(*(__half2*)&g[u].z);
                float2 f3 = __half22float2(*(__half2*)&g[u].w);
                acc[0] += f0.x; acc[1] += f0.y; acc[2] += f1.x; acc[3] += f1.y;
                acc[4] += f2.x; acc[5] += f2.y; acc[6] += f3.x; acc[7] += f3.y;
            }
        }
    }

    // combine quarters
#pragma unroll
    for (int i = 0; i < 8; i++) {
        acc[i] += __shfl_xor_sync(0xffffffffu, acc[i], 8);
        acc[i] += __shfl_xor_sync(0xffffffffu, acc[i], 16);
    }

    float s = d_dis[v];
    if (q == 0) {
        float4 ba = *(const float4*)(b1 + ql * 8);
        float4 bb = *(const float4*)(b1 + ql * 8 + 4);
        float pre[8];
        pre[0] = s * acc[0] + ba.x; pre[1] = s * acc[1] + ba.y;
        pre[2] = s * acc[2] + ba.z; pre[3] = s * acc[3] + ba.w;
        pre[4] = s * acc[4] + bb.x; pre[5] = s * acc[5] + bb.y;
        pre[6] = s * acc[6] + bb.z; pre[7] = s * acc[7] + bb.w;
        float h[8];
#pragma unroll
        for (int i = 0; i < 8; i++) h[i] = pre[i] > 0.f ? pre[i] : expm1f(pre[i]);
        *(float4*)&sh[warp][ql * 8]     = make_float4(h[0], h[1], h[2], h[3]);
        *(float4*)&sh[warp][ql * 8 + 4] = make_float4(h[4], h[5], h[6], h[7]);
    }
    __syncwarp();

    // GEMM2 for this node: out[o=lane] = sum_f h[f] * W2[f][o]
    float o_acc = 0.f;
#pragma unroll
    for (int f = 0; f < 64; f++) o_acc = fmaf(sh[warp][f], sW[f][lane], o_acc);
    float val = s * o_acc;
    float vnext = __shfl_down_sync(0xffffffffu, val, 1);
    if (!(lane & 1)) {
        __half2 h = __floats2half2_rn(val, vnext);
        d_g2h[(size_t)v * 16 + (lane >> 1)] = *(unsigned*)&h;
    }
}

// ---------------- agg2: 4 edges/warp via quarter-warps, uint2/lane + ELU + dot(Wc) ----------------
__global__ __launch_bounds__(256) void k_agg2(const float* __restrict__ b2,
                                              const float* __restrict__ Wc,
                                              const float* __restrict__ bc,
                                              float* __restrict__ out) {
    int t = threadIdx.x;
    int warp = t >> 5;
    int lane = t & 31;
    int v = blockIdx.x * 8 + warp;
    if (v >= NN) return;

    int start = d_off[v];
    int cnt = d_cnt[v];
    int q = lane >> 3;
    int ql = lane & 7;      // owns features [ql*4, ql*4+4)

    float acc[4];
#pragma unroll
    for (int i = 0; i < 4; i++) acc[i] = 0.f;
    if (q == 0) {
        uint2 sv = *(const uint2*)&d_g2h[(size_t)v * 16 + ql * 2];
        float2 f0 = __half22float2(*(__half2*)&sv.x);
        float2 f1 = __half22float2(*(__half2*)&sv.y);
        acc[0] = f0.x; acc[1] = f0.y; acc[2] = f1.x; acc[3] = f1.y;
    }

    for (int base = 0; base < cnt; base += 32) {
        int nb = cnt - base; if (nb > 32) nb = 32;
        int er = (lane < nb) ? d_erow[start + base + lane] : 0;
        uint2 g[8];
        bool pv[8];
#pragma unroll
        for (int u = 0; u < 8; u++) {
            int jj = 4 * u + q;
            int r = __shfl_sync(0xffffffffu, er, jj);
            pv[u] = jj < nb;
            r = pv[u] ? r : v;
            g[u] = *(const uint2*)&d_g2h[(size_t)r * 16 + ql * 2];
        }
#pragma unroll
        for (int u = 0; u < 8; u++) {
            if (pv[u]) {
                float2 f0 = __half22float2(*(__half2*)&g[u].x);
                float2 f1 = __half22float2(*(__half2*)&g[u].y);
                acc[0] += f0.x; acc[1] += f0.y; acc[2] += f1.x; acc[3] += f1.y;
            }
        }
    }

#pragma unroll
    for (int i = 0; i < 4; i++) {
        acc[i] += __shfl_xor_sync(0xffffffffu, acc[i], 8);
        acc[i] += __shfl_xor_sync(0xffffffffu, acc[i], 16);
    }

    float p = 0.f;
    if (q == 0) {
        float s = d_dis[v];
        float4 bb = *(const float4*)(b2 + ql * 4);
        float4 wc = *(const float4*)(Wc + ql * 4);
        float pre0 = s * acc[0] + bb.x;
        float pre1 = s * acc[1] + bb.y;
        float pre2 = s * acc[2] + bb.z;
        float pre3 = s * acc[3] + bb.w;
        float h0 = pre0 > 0.f ? pre0 : expm1f(pre0);
        float h1 = pre1 > 0.f ? pre1 : expm1f(pre1);
        float h2 = pre2 > 0.f ? pre2 : expm1f(pre2);
        float h3 = pre3 > 0.f ? pre3 : expm1f(pre3);
        p = h0 * wc.x + h1 * wc.y + h2 * wc.z + h3 * wc.w;
    }
#pragma unroll
    for (int off = 16; off; off >>= 1) p += __shfl_xor_sync(0xffffffffu, p, off);
    if (lane == 0) out[v] = p + bc[0];
}

// ---------------- launch ----------------
extern "C" void kernel_launch(void* const* d_in, const int* in_sizes, int n_in,
                              void* d_out, int out_size) {
    const float* x  = (const float*)d_in[0];
    const void*  ei = d_in[1];                 // [2,E], int32 or int64 (auto-detected)
    const float* W1 = (const float*)d_in[2];
    const float* b1 = (const float*)d_in[3];
    const float* W2 = (const float*)d_in[4];
    const float* b2 = (const float*)d_in[5];
    const float* Wc = (const float*)d_in[6];
    const float* bc = (const float*)d_in[7];
    float*       out = (float*)d_out;

    k_zero<<<(NN + 255) / 256, 256>>>((const int*)ei);
    k_hist<<<(EE / 4 + 255) / 256, 256>>>(ei);
    k_bsum<<<NBLK, SCAN_B>>>();
    k_off<<<NBLK, SCAN_B>>>();
    k_fill<<<(EE / 4 + 255) / 256, 256>>>(ei);
    k_gemm1<<<(NN + 63) / 64, 128>>>(x, W1);
    k_agg1<<<(NN + 7) / 8, 256>>>(b1, W2);
    k_agg2<<<(NN + 7) / 8, 256>>>(b2, Wc, bc, out);
}